// round 16
// baseline (speedup 1.0000x reference)
#include <cuda_runtime.h>
#include <cuda_fp16.h>
#include <cstdint>

#define NUM_EXPERTS 8
#define HIDDEN 1024
#define INTER 4096
#define NTOK 2048
#define SOFTCAPV 30.0f
#define MAXROWS (NTOK * 2)

// ---------------- scratch (device globals; no allocs allowed) ----------------
__device__ int    g_counts[NUM_EXPERTS];
__device__ int    g_base[NUM_EXPERTS];
__device__ int    g_row_token[MAXROWS];
__device__ float  g_row_weight[MAXROWS];
__device__ int    g_tok_e[NTOK * 2];
__device__ float  g_tok_w[NTOK * 2];
__device__ __align__(16) __half g_w1h[(size_t)NUM_EXPERTS * INTER * HIDDEN];  // 64 MB
__device__ __align__(16) __half g_w3h[(size_t)NUM_EXPERTS * INTER * HIDDEN];  // 64 MB
__device__ __align__(16) __half g_w2h[(size_t)NUM_EXPERTS * HIDDEN * INTER];  // 64 MB
__device__ __align__(16) __half g_xh[(size_t)NTOK * HIDDEN];                  // 4 MB
__device__ __align__(16) __half g_act[(size_t)MAXROWS * INTER];               // 32 MB

// ---------------- helpers ----------------
__device__ __forceinline__ void mma_f16(float* c, const uint32_t* a, const uint32_t* b) {
    asm volatile(
        "mma.sync.aligned.m16n8k16.row.col.f32.f16.f16.f32 "
        "{%0,%1,%2,%3},{%4,%5,%6,%7},{%8,%9},{%0,%1,%2,%3};"
        : "+f"(c[0]), "+f"(c[1]), "+f"(c[2]), "+f"(c[3])
        : "r"(a[0]), "r"(a[1]), "r"(a[2]), "r"(a[3]), "r"(b[0]), "r"(b[1]));
}
__device__ __forceinline__ uint32_t f2h2(float a, float b) {
    uint32_t r;
    asm("cvt.rn.f16x2.f32 %0, %1, %2;" : "=r"(r) : "f"(b), "f"(a));
    return r;
}
__device__ __forceinline__ void cp_async16(uint32_t dst, const void* src, int src_sz) {
    asm volatile("cp.async.cg.shared.global [%0], [%1], 16, %2;\n"
                 :: "r"(dst), "l"(src), "r"(src_sz));
}
__device__ __forceinline__ uint32_t smem_u32(const void* p) {
    uint32_t a;
    asm("{ .reg .u64 t; cvta.to.shared.u64 t, %1; cvt.u32.u64 %0, t; }"
        : "=r"(a) : "l"(p));
    return a;
}
__device__ __forceinline__ void ldsm4(uint32_t* r, uint32_t addr) {
    asm volatile("ldmatrix.sync.aligned.m8n8.x4.shared.b16 {%0,%1,%2,%3}, [%4];"
                 : "=r"(r[0]), "=r"(r[1]), "=r"(r[2]), "=r"(r[3]) : "r"(addr));
}
__device__ __forceinline__ float gelu_exact(float v) {
    return 0.5f * v * (1.f + erff(v * 0.70710678118654752f));
}

// ---------------- convert w1 + w3 in one kernel ----------------
__global__ void k_cvtw13(const float4* __restrict__ w1, const float4* __restrict__ w3,
                         int n4) {
    uint2* d1 = (uint2*)g_w1h;
    uint2* d3 = (uint2*)g_w3h;
    int i = blockIdx.x * blockDim.x + threadIdx.x;
    int stride = gridDim.x * blockDim.x;
    for (; i < n4; i += stride) {
        float4 v = w1[i];
        d1[i] = make_uint2(f2h2(v.x, v.y), f2h2(v.z, v.w));
        float4 u = w3[i];
        d3[i] = make_uint2(f2h2(u.x, u.y), f2h2(u.z, u.w));
    }
}
__global__ void k_cvtw2(const float4* __restrict__ w2, int n4) {
    uint2* d = (uint2*)g_w2h;
    int i = blockIdx.x * blockDim.x + threadIdx.x;
    int stride = gridDim.x * blockDim.x;
    for (; i < n4; i += stride) {
        float4 v = w2[i];
        d[i] = make_uint2(f2h2(v.x, v.y), f2h2(v.z, v.w));
    }
}

// ---------------- setup: zero output + x->f16 + router ----------------
__global__ void k_setup(const float* __restrict__ x, const float* __restrict__ wg,
                        float* __restrict__ out) {
    int gtid = blockIdx.x * blockDim.x + threadIdx.x;   // 65536 threads
    float4* o4 = (float4*)out;
    const float4* x4 = (const float4*)x;
    uint2* xh2 = (uint2*)g_xh;
#pragma unroll
    for (int j = 0; j < 8; j++) {
        o4[gtid * 8 + j] = make_float4(0.f, 0.f, 0.f, 0.f);
        float4 v = x4[gtid * 8 + j];
        xh2[gtid * 8 + j] = make_uint2(f2h2(v.x, v.y), f2h2(v.z, v.w));
    }

    int warp = gtid >> 5;            // 2048 warps = tokens
    int lane = threadIdx.x & 31;
    const float* xr = x + (size_t)warp * HIDDEN;
    float acc[NUM_EXPERTS];
#pragma unroll
    for (int e = 0; e < NUM_EXPERTS; e++) acc[e] = 0.f;
    for (int h = lane; h < HIDDEN; h += 32) {
        float xv = xr[h];
#pragma unroll
        for (int e = 0; e < NUM_EXPERTS; e++) acc[e] += xv * wg[e * HIDDEN + h];
    }
#pragma unroll
    for (int off = 16; off; off >>= 1)
#pragma unroll
        for (int e = 0; e < NUM_EXPERTS; e++)
            acc[e] += __shfl_xor_sync(0xffffffffu, acc[e], off);
    if (lane == 0) {
        float l[NUM_EXPERTS];
#pragma unroll
        for (int e = 0; e < NUM_EXPERTS; e++)
            l[e] = SOFTCAPV * tanhf(acc[e] / SOFTCAPV);
        int b = 0; float vb = l[0];
#pragma unroll
        for (int e = 1; e < NUM_EXPERTS; e++) if (l[e] > vb) { b = e; vb = l[e]; }
        int s = -1; float vs = -1e30f;
#pragma unroll
        for (int e = 0; e < NUM_EXPERTS; e++)
            if (e != b && l[e] > vs) { s = e; vs = l[e]; }
        float wa = 1.f / (1.f + expf(vs - vb));   // 2-way softmax == softmax+renorm
        g_tok_e[2 * warp]     = b;  g_tok_w[2 * warp]     = wa;
        g_tok_e[2 * warp + 1] = s;  g_tok_w[2 * warp + 1] = 1.f - wa;
    }
}

// ---------------- plan: counts + prefix + scatter (single block) -------------
__global__ void k_plan() {
    __shared__ int sc[NUM_EXPERTS], sb[NUM_EXPERTS], sf[NUM_EXPERTS];
    int tid = threadIdx.x;
    if (tid < NUM_EXPERTS) { sc[tid] = 0; sf[tid] = 0; }
    __syncthreads();
    for (int i = tid; i < 2 * NTOK; i += blockDim.x)
        atomicAdd(&sc[g_tok_e[i]], 1);
    __syncthreads();
    if (tid == 0) {
        int acc = 0;
        for (int e = 0; e < NUM_EXPERTS; e++) {
            sb[e] = acc; g_base[e] = acc; g_counts[e] = sc[e]; acc += sc[e];
        }
    }
    __syncthreads();
    for (int i = tid; i < 2 * NTOK; i += blockDim.x) {
        int e = g_tok_e[i];
        int p = atomicAdd(&sf[e], 1);
        int r = sb[e] + p;
        g_row_token[r]  = i >> 1;
        g_row_weight[r] = g_tok_w[i];
    }
}

// ---------------- tiling ----------------
#define BM 128
#define BN 128
#define BK 32
#define NSTAGE 4
#define A_ST (BM * BK * 2)            // 8192 B
#define B_ST (BN * BK * 2)            // 8192 B
#define STG13 (A_ST + 2 * B_ST)       // 24576 B
#define SMEM13 (NSTAGE * STG13)       // 98304 B
#define STG2 (A_ST + B_ST)            // 16384 B
#define SMEM2 (NSTAGE * STG2)         // 65536 B

// swizzled chunk byte offset inside a tile: row, ch(0..3) of 16B (64B rows)
__device__ __forceinline__ uint32_t swz(int row, int ch) {
    return (uint32_t)(row * 64 + ((ch ^ ((row >> 1) & 3)) << 4));
}

// ---------------- fused up-proj: g_act = gelu(x@w1^T) * (x@w3^T) -------------
__global__ void __launch_bounds__(256, 1) k_gemm13() {
    int e   = blockIdx.z;
    int cnt = g_counts[e];
    int m0  = blockIdx.x * BM;          // m fastest: concurrent CTAs share B in L2
    if (m0 >= cnt) return;
    int n0    = blockIdx.y * BN;
    int rbase = g_base[e];
    const __half* B1 = g_w1h + (size_t)e * INTER * HIDDEN;
    const __half* B3 = g_w3h + (size_t)e * INTER * HIDDEN;

    extern __shared__ __align__(16) char smem[];
    uint32_t sbase = smem_u32(smem);

    int tid  = threadIdx.x;
    int lane = tid & 31, warp = tid >> 5;   // 8 warps: 2(m) x 4(n); tile 64x32 per B
    int wm = warp & 1, wn = warp >> 1;

    // ---- loader: per thread per stage, 16B chunks: A x2, B1 x2, B3 x2 ----
    const __half* aptr[2]; int asz[2]; uint32_t coff[2];
    const __half* b1ptr[2]; const __half* b3ptr[2];
#pragma unroll
    for (int p = 0; p < 2; p++) {
        int id  = tid + p * 256;        // 0..511 = 128 rows x 4 chunks
        int row = id >> 2, ch = id & 3;
        int mg  = m0 + row;
        int t = (mg < cnt) ? g_row_token[rbase + mg] : 0;
        aptr[p] = g_xh + (size_t)t * HIDDEN + ch * 8;
        asz[p]  = (mg < cnt) ? 16 : 0;
        b1ptr[p] = B1 + (size_t)(n0 + row) * HIDDEN + ch * 8;
        b3ptr[p] = B3 + (size_t)(n0 + row) * HIDDEN + ch * 8;
        coff[p] = swz(row, ch);
    }

    auto issue = [&](int kt, int st) {
        uint32_t sA  = sbase + st * STG13;
        uint32_t sB1 = sA + A_ST;
        uint32_t sB3 = sB1 + B_ST;
        int k0 = kt * BK;
#pragma unroll
        for (int p = 0; p < 2; p++) {
            cp_async16(sA + coff[p], aptr[p] + k0, asz[p]);
            cp_async16(sB1 + coff[p], b1ptr[p] + k0, 16);
            cp_async16(sB3 + coff[p], b3ptr[p] + k0, 16);
        }
        asm volatile("cp.async.commit_group;\n");
    };

    // ---- ldmatrix lane addressing ----
    int q  = lane >> 3;
    int qr = (q & 1) * 8 + (lane & 7);
    int cq = q >> 1;
    int rA0 = wm * 64 + qr;
    int rB0 = wn * 32 + qr;
    int swzA = (rA0 >> 1) & 3;
    int swzB = (rB0 >> 1) & 3;
    uint32_t offA[2], offB[2];
#pragma unroll
    for (int kk = 0; kk < 2; kk++) {
        offA[kk] = (uint32_t)(rA0 * 64 + (((2 * kk + cq) ^ swzA) << 4));
        offB[kk] = (uint32_t)(rB0 * 64 + (((2 * kk + cq) ^ swzB) << 4));
    }

    float acc1[4][4][4], acc3[4][4][4];
#pragma unroll
    for (int i = 0; i < 4; i++)
#pragma unroll
        for (int j = 0; j < 4; j++)
#pragma unroll
            for (int c = 0; c < 4; c++) { acc1[i][j][c] = 0.f; acc3[i][j][c] = 0.f; }

    uint32_t a[2][4][4], b1f[2][4][2], b3f[2][4][2];
    auto ldfrag = [&](uint32_t aS, uint32_t b1S, uint32_t b3S, int kk, int buf) {
#pragma unroll
        for (int mt = 0; mt < 4; mt++)
            ldsm4(a[buf][mt], aS + offA[kk] + mt * 1024);
#pragma unroll
        for (int g2 = 0; g2 < 2; g2++) {
            uint32_t r[4];
            ldsm4(r, b1S + offB[kk] + g2 * 1024);
            b1f[buf][2 * g2][0] = r[0]; b1f[buf][2 * g2][1] = r[2];
            b1f[buf][2 * g2 + 1][0] = r[1]; b1f[buf][2 * g2 + 1][1] = r[3];
            ldsm4(r, b3S + offB[kk] + g2 * 1024);
            b3f[buf][2 * g2][0] = r[0]; b3f[buf][2 * g2][1] = r[2];
            b3f[buf][2 * g2 + 1][0] = r[1]; b3f[buf][2 * g2 + 1][1] = r[3];
        }
    };

    constexpr int KT = HIDDEN / BK;     // 32
    issue(0, 0);
    issue(1, 1);
    issue(2, 2);
    int s = 0;
    for (int kt = 0; kt < KT; kt++) {
        if (kt + 2 < KT) {
            asm volatile("cp.async.wait_group 2;\n" ::: "memory");
        } else if (kt + 1 < KT) {
            asm volatile("cp.async.wait_group 1;\n" ::: "memory");
        } else {
            asm volatile("cp.async.wait_group 0;\n" ::: "memory");
        }
        __syncthreads();
        if (kt + 3 < KT) {
            int s3 = (s >= 1) ? s - 1 : 3;      // (s+3)%4
            issue(kt + 3, s3);
        }
        uint32_t aS  = sbase + s * STG13;
        uint32_t b1S = aS + A_ST;
        uint32_t b3S = b1S + B_ST;
        ldfrag(aS, b1S, b3S, 0, 0);
        ldfrag(aS, b1S, b3S, 1, 1);
#pragma unroll
        for (int kk = 0; kk < 2; kk++)
#pragma unroll
            for (int mt = 0; mt < 4; mt++)
#pragma unroll
                for (int nt = 0; nt < 4; nt++) {
                    mma_f16(acc1[mt][nt], a[kk][mt], b1f[kk][nt]);
                    mma_f16(acc3[mt][nt], a[kk][mt], b3f[kk][nt]);
                }
        s = (s == 3) ? 0 : s + 1;
    }

    // ---- epilogue: gelu(h1)*h3 -> f16 g_act ----
    int lr = lane >> 2, lc = lane & 3;
#pragma unroll
    for (int mt = 0; mt < 4; mt++) {
#pragma unroll
        for (int rh = 0; rh < 2; rh++) {
            int row = wm * 64 + mt * 16 + lr + rh * 8;
            int mg  = m0 + row;
            if (mg >= cnt) continue;
            int gr = rbase + mg;
#pragma unroll
            for (int nt = 0; nt < 4; nt++) {
                int col = n0 + wn * 32 + nt * 8 + lc * 2;
                float h10 = acc1[mt][nt][2 * rh], h11 = acc1[mt][nt][2 * rh + 1];
                float h30 = acc3[mt][nt][2 * rh], h31 = acc3[mt][nt][2 * rh + 1];
                *(uint32_t*)&g_act[(size_t)gr * INTER + col] =
                    f2h2(gelu_exact(h10) * h30, gelu_exact(h11) * h31);
            }
        }
    }
}

// ---------------- down-proj: out[token] += w * (act @ w2^T) ------------------
__global__ void __launch_bounds__(256, 1) k_gemm2(float* __restrict__ Out) {
    int e   = blockIdx.z;
    int cnt = g_counts[e];
    int m0  = blockIdx.x * BM;
    if (m0 >= cnt) return;
    int n0    = blockIdx.y * BN;
    int rbase = g_base[e];
    const __half* B = g_w2h + (size_t)e * HIDDEN * INTER;

    extern __shared__ __align__(16) char smem[];
    uint32_t sbase = smem_u32(smem);

    int tid  = threadIdx.x;
    int lane = tid & 31, warp = tid >> 5;   // 8 warps: 2(m) x 4(n), warp tile 64x32
    int wm = warp & 1, wn = warp >> 1;

    const __half* aptr[2]; int asz[2]; uint32_t coff[2];
    const __half* bptr[2];
#pragma unroll
    for (int p = 0; p < 2; p++) {
        int id  = tid + p * 256;
        int row = id >> 2, ch = id & 3;
        int mg  = m0 + row;
        int rr  = rbase + (mg < cnt ? mg : 0);
        aptr[p] = g_act + (size_t)rr * INTER + ch * 8;
        asz[p]  = (mg < cnt) ? 16 : 0;
        bptr[p] = B + (size_t)(n0 + row) * INTER + ch * 8;
        coff[p] = swz(row, ch);
    }

    auto issue = [&](int kt, int st) {
        uint32_t sA = sbase + st * STG2;
        uint32_t sB = sA + A_ST;
        int k0 = kt * BK;
#pragma unroll
        for (int p = 0; p < 2; p++) {
            cp_async16(sA + coff[p], aptr[p] + k0, asz[p]);
            cp_async16(sB + coff[p], bptr[p] + k0, 16);
        }
        asm volatile("cp.async.commit_group;\n");
    };

    int q  = lane >> 3;
    int qr = (q & 1) * 8 + (lane & 7);
    int cq = q >> 1;
    int rA0 = wm * 64 + qr;
    int rB0 = wn * 32 + qr;
    int swzA = (rA0 >> 1) & 3;
    int swzB = (rB0 >> 1) & 3;
    uint32_t offA[2], offB[2];
#pragma unroll
    for (int kk = 0; kk < 2; kk++) {
        offA[kk] = (uint32_t)(rA0 * 64 + (((2 * kk + cq) ^ swzA) << 4));
        offB[kk] = (uint32_t)(rB0 * 64 + (((2 * kk + cq) ^ swzB) << 4));
    }

    float acc[4][4][4];
#pragma unroll
    for (int i = 0; i < 4; i++)
#pragma unroll
        for (int j = 0; j < 4; j++)
#pragma unroll
            for (int c = 0; c < 4; c++) acc[i][j][c] = 0.f;

    uint32_t a[2][4][4], bf[2][4][2];
    auto ldfrag = [&](uint32_t aS, uint32_t bS, int kk, int buf) {
#pragma unroll
        for (int mt = 0; mt < 4; mt++)
            ldsm4(a[buf][mt], aS + offA[kk] + mt * 1024);
#pragma unroll
        for (int g2 = 0; g2 < 2; g2++) {
            uint32_t r[4];
            ldsm4(r, bS + offB[kk] + g2 * 1024);
            bf[buf][2 * g2][0] = r[0]; bf[buf][2 * g2][1] = r[2];
            bf[buf][2 * g2 + 1][0] = r[1]; bf[buf][2 * g2 + 1][1] = r[3];
        }
    };

    constexpr int KT = INTER / BK;      // 128
    issue(0, 0);
    issue(1, 1);
    issue(2, 2);
    int s = 0;
    for (int kt = 0; kt < KT; kt++) {
        if (kt + 2 < KT) {
            asm volatile("cp.async.wait_group 2;\n" ::: "memory");
        } else if (kt + 1 < KT) {
            asm volatile("cp.async.wait_group 1;\n" ::: "memory");
        } else {
            asm volatile("cp.async.wait_group 0;\n" ::: "memory");
        }
        __syncthreads();
        if (kt + 3 < KT) {
            int s3 = (s >= 1) ? s - 1 : 3;
            issue(kt + 3, s3);
        }
        uint32_t aS = sbase + s * STG2;
        uint32_t bS = aS + A_ST;
        ldfrag(aS, bS, 0, 0);
        ldfrag(aS, bS, 1, 1);
#pragma unroll
        for (int kk = 0; kk < 2; kk++)
#pragma unroll
            for (int mt = 0; mt < 4; mt++)
#pragma unroll
                for (int nt = 0; nt < 4; nt++)
                    mma_f16(acc[mt][nt], a[kk][mt], bf[kk][nt]);
        s = (s == 3) ? 0 : s + 1;
    }

    int lr = lane >> 2, lc = lane & 3;
#pragma unroll
    for (int mt = 0; mt < 4; mt++) {
#pragma unroll
        for (int rh = 0; rh < 2; rh++) {
            int row = wm * 64 + mt * 16 + lr + rh * 8;
            int mg  = m0 + row;
            if (mg >= cnt) continue;
            int gr = rbase + mg;
            int t  = g_row_token[gr];
            float wgt = g_row_weight[gr];
#pragma unroll
            for (int nt = 0; nt < 4; nt++) {
                int col = n0 + wn * 32 + nt * 8 + lc * 2;
                float* op = Out + (size_t)t * HIDDEN + col;
                atomicAdd(op, wgt * acc[mt][nt][2 * rh]);
                atomicAdd(op + 1, wgt * acc[mt][nt][2 * rh + 1]);
            }
        }
    }
}

// ---------------- launch ----------------
extern "C" void kernel_launch(void* const* d_in, const int* in_sizes, int n_in,
                              void* d_out, int out_size) {
    const float* x  = (const float*)d_in[0];
    const float* wg = (const float*)d_in[1];
    const float* w1 = (const float*)d_in[2];
    const float* w3 = (const float*)d_in[3];
    const float* w2 = (const float*)d_in[4];
    float* out = (float*)d_out;

    cudaFuncSetAttribute(k_gemm13, cudaFuncAttributeMaxDynamicSharedMemorySize, SMEM13);
    cudaFuncSetAttribute(k_gemm2,  cudaFuncAttributeMaxDynamicSharedMemorySize, SMEM2);

    const int W4 = NUM_EXPERTS * INTER * HIDDEN / 4;   // 8M float4

    k_setup<<<256, 256>>>(x, wg, out);                              // #1
    k_plan<<<1, 512>>>();                                           // #2
    k_cvtw13<<<4096, 256>>>((const float4*)w1, (const float4*)w3, W4);  // #3

    dim3 g13(NTOK / BM, INTER / BN, NUM_EXPERTS);      // 16 x 32 x 8
    k_gemm13<<<g13, 256, SMEM13>>>();                  // #4  <- ncu lands here

    k_cvtw2<<<2048, 256>>>((const float4*)w2, W4);     // #5
    dim3 g2(NTOK / BM, HIDDEN / BN, NUM_EXPERTS);      // 16 x 8 x 8
    k_gemm2<<<g2, 256, SMEM2>>>(out);                  // #6
}